// round 14
// baseline (speedup 1.0000x reference)
#include <cuda_runtime.h>
#include <cuda_bf16.h>
#include <math.h>
#include <stdint.h>

#define N_NODES 50000
#define N_EDGES 400000
#define DIM     512
#define LAYERS  3
#define INNER   2048      // (LAYERS+1)*DIM
#define EPSBN   1e-5f

// ---------------- static device scratch (no allocations allowed) ----------------
__device__ __nv_bfloat16 g_xch[(size_t)N_NODES * INNER];  // bf16 hi plane of xc
__device__ __nv_bfloat16 g_xcl[(size_t)N_NODES * INNER];  // bf16 lo plane of xc
__device__ float g_t  [(size_t)N_NODES * DIM];     // h @ W (layer GEMM out, fp32)
__device__ float g_dinv[N_NODES];
__device__ int   g_cnt [N_NODES];                  // in-degree
__device__ int   g_rowptr[N_NODES + 1];
__device__ int   g_fill[N_NODES];
__device__ int   g_esrc[N_EDGES];                  // CSR: src node per (dst-sorted) edge
__device__ float g_sum  [INNER];
__device__ float g_sumsq[INNER];
__device__ float g_scale[INNER];
__device__ float g_shift[INNER];
__device__ float g_biasp[DIM];                     // shift-folded head bias
// transposed + split weights: Bt[n, k] (K-major rows)
__device__ __nv_bfloat16 g_Wth[(size_t)LAYERS * DIM * DIM];
__device__ __nv_bfloat16 g_Wtl[(size_t)LAYERS * DIM * DIM];
__device__ __nv_bfloat16 g_Wpth[(size_t)DIM * INNER];   // head: [512, 2048]
__device__ __nv_bfloat16 g_Wptl[(size_t)DIM * INNER];

// ---------------- helpers ----------------
__device__ __forceinline__ float gelu_exact(float v) {
    return 0.5f * v * (1.0f + erff(v * 0.70710678118654752440f));
}

__device__ __forceinline__ uint32_t smem_u32(const void* p) {
    uint32_t a;
    asm("{ .reg .u64 t; cvta.to.shared.u64 t, %1; cvt.u32.u64 %0, t; }" : "=r"(a) : "l"(p));
    return a;
}

// split fp32 -> bf16 hi + bf16 lo (packed 4-wide)
__device__ __forceinline__ void split4(float4 v, uint2& uh, uint2& ul) {
    union { __nv_bfloat16 b[4]; uint2 u; } H, L;
    H.b[0] = __float2bfloat16(v.x); L.b[0] = __float2bfloat16(v.x - __bfloat162float(H.b[0]));
    H.b[1] = __float2bfloat16(v.y); L.b[1] = __float2bfloat16(v.y - __bfloat162float(H.b[1]));
    H.b[2] = __float2bfloat16(v.z); L.b[2] = __float2bfloat16(v.z - __bfloat162float(H.b[2]));
    H.b[3] = __float2bfloat16(v.w); L.b[3] = __float2bfloat16(v.w - __bfloat162float(H.b[3]));
    uh = H.u; ul = L.u;
}

__device__ __forceinline__ void ldsm4(uint32_t addr, uint32_t& r0, uint32_t& r1,
                                      uint32_t& r2, uint32_t& r3) {
    asm volatile("ldmatrix.sync.aligned.m8n8.x4.shared.b16 {%0,%1,%2,%3}, [%4];"
                 : "=r"(r0), "=r"(r1), "=r"(r2), "=r"(r3) : "r"(addr));
}

__device__ __forceinline__ void mma16816(float* c, const uint32_t* a,
                                         uint32_t b0, uint32_t b1) {
    asm volatile(
        "mma.sync.aligned.m16n8k16.row.col.f32.bf16.bf16.f32 "
        "{%0,%1,%2,%3}, {%4,%5,%6,%7}, {%8,%9}, {%0,%1,%2,%3};"
        : "+f"(c[0]), "+f"(c[1]), "+f"(c[2]), "+f"(c[3])
        : "r"(a[0]), "r"(a[1]), "r"(a[2]), "r"(a[3]), "r"(b0), "r"(b1));
}

// ---------------- CSR build ----------------
__global__ void zero_int_kernel() {
    int n = blockIdx.x * blockDim.x + threadIdx.x;
    if (n < N_NODES) { g_cnt[n] = 0; g_fill[n] = 0; }
}
__global__ void count_kernel(const int* __restrict__ ei) {
    int e = blockIdx.x * blockDim.x + threadIdx.x;
    if (e < N_EDGES) atomicAdd(&g_cnt[ei[N_EDGES + e]], 1);
}
__global__ void scan_kernel() {
    __shared__ int partial[1024];
    const int t = threadIdx.x;
    const int chunk = (N_NODES + 1023) / 1024;
    const int start = t * chunk;
    const int end = min(start + chunk, N_NODES);
    int s = 0;
    for (int i = start; i < end; i++) s += g_cnt[i];
    partial[t] = s;
    __syncthreads();
    #pragma unroll
    for (int off = 1; off < 1024; off <<= 1) {
        int v = (t >= off) ? partial[t - off] : 0;
        __syncthreads();
        partial[t] += v;
        __syncthreads();
    }
    int run = partial[t] - s;
    for (int i = start; i < end; i++) { g_rowptr[i] = run; run += g_cnt[i]; }
    if (t == 1023) g_rowptr[N_NODES] = run;
}
__global__ void fill_kernel(const int* __restrict__ ei) {
    int e = blockIdx.x * blockDim.x + threadIdx.x;
    if (e < N_EDGES) {
        int s = ei[e];
        int d = ei[N_EDGES + e];
        int pos = g_rowptr[d] + atomicAdd(&g_fill[d], 1);
        g_esrc[pos] = s;
    }
}
__global__ void dinv_kernel() {
    int n = blockIdx.x * blockDim.x + threadIdx.x;
    if (n < N_NODES) g_dinv[n] = rsqrtf((float)g_cnt[n] + 1.0f);
}

__global__ void zero_stats_kernel() {
    int c = blockIdx.x * blockDim.x + threadIdx.x;
    if (c < INNER) { g_sum[c] = 0.0f; g_sumsq[c] = 0.0f; }
}

// ---------------- copy x into concat slab 0 (bf16 hi/lo planes) ----------------
__global__ void copy_x_kernel(const float* __restrict__ x) {
    int i = blockIdx.x * blockDim.x + threadIdx.x;    // N_NODES*128 float4 units
    int n = i >> 7;
    int c = (i & 127) << 2;
    float4 v = *(const float4*)(x + (size_t)n * DIM + c);
    size_t o = (size_t)n * INNER + c;
    uint2 uh, ul; split4(v, uh, ul);
    *(uint2*)(g_xch + o) = uh;
    *(uint2*)(g_xcl + o) = ul;
}

// ---------------- transpose+split layer weights: Wt[l][n][k] = W[l][k][n] ----------------
__global__ void wt_kernel(const float* __restrict__ Ws) {
    int i = blockIdx.x * blockDim.x + threadIdx.x;    // 3*512*512
    if (i >= LAYERS * DIM * DIM) return;
    int l = i >> 18, rem = i & 262143, k = rem >> 9, n = rem & 511;
    float w = Ws[(size_t)l * DIM * DIM + (size_t)k * DIM + n];
    __nv_bfloat16 h = __float2bfloat16(w);
    size_t o = (size_t)l * DIM * DIM + (size_t)n * DIM + k;
    g_Wth[o] = h;
    g_Wtl[o] = __float2bfloat16(w - __bfloat162float(h));
}

// ---------------- scaled head weight transpose+split ----------------
__global__ void wpt_kernel(const float* __restrict__ outW) {
    int i = blockIdx.x * blockDim.x + threadIdx.x;    // 2048*512
    if (i >= INNER * DIM) return;
    int k = i >> 9, n = i & 511;
    float w = outW[i] * g_scale[k];
    __nv_bfloat16 h = __float2bfloat16(w);
    size_t o = (size_t)n * INNER + k;
    g_Wpth[o] = h;
    g_Wptl[o] = __float2bfloat16(w - __bfloat162float(h));
}

// ---------------- cp.async 3-stage split-bf16 GEMM, single barrier per K-step ----------------
// Tile 128x128, K_tile=16, 3 stages. SMEM: 3 x 4 tiles x 128 rows x 48B stride = 72KB dynamic.
// Mainloop order: wait -> sync -> issue(it+2) -> compute(it). Issue targets buffer (it-1)%3,
// safe because all warps passing barrier #it have finished compute(it-1).
#define TSTRIDE 48
#define TILE_SZ (128 * TSTRIDE)      // 6144
#define STAGE_SZ (4 * TILE_SZ)       // 24576
#define NSTAGE 3
#define GEMM_SMEM (NSTAGE * STAGE_SZ)   // 73728

__global__ __launch_bounds__(256)
void mma_gemm_kernel(const __nv_bfloat16* __restrict__ Ahi, const __nv_bfloat16* __restrict__ Alo,
                     const __nv_bfloat16* __restrict__ Bhi, const __nv_bfloat16* __restrict__ Blo,
                     const float* __restrict__ bias, float* __restrict__ C,
                     int M, int K, int lda, int ldb, int ldc, int has_bias)
{
    extern __shared__ char smem[];

    const int tid = threadIdx.x, wid = tid >> 5, lane = tid & 31;
    const int bm = blockIdx.y * 128, bn = blockIdx.x * 128;
    const int warp_m = (wid & 3) * 32, warp_n = (wid >> 2) * 64;
    const uint32_t sbase = smem_u32(smem);

    float acc[2][8][4];
    #pragma unroll
    for (int a = 0; a < 2; a++)
        #pragma unroll
        for (int b = 0; b < 8; b++)
            #pragma unroll
            for (int c = 0; c < 4; c++) acc[a][b][c] = 0.0f;

    const uint32_t aoff = (uint32_t)(((lane & 7) + ((lane >> 3) & 1) * 8) * TSTRIDE + (lane >> 4) * 16);
    const uint32_t boff = (uint32_t)(((lane & 7) + (lane >> 4) * 8) * TSTRIDE + ((lane >> 3) & 1) * 16);

    // per-thread fixed load assignment: (row = tid>>1, half = tid&1), tiles Ah,Al,Bh,Bl
    const int lrow = tid >> 1, lhalf = tid & 1;
    int ra = bm + lrow;
    const int asz = (ra < M) ? 16 : 0;
    if (ra >= M) ra = 0;
    const int rb = bn + lrow;
    const __nv_bfloat16* pAh = Ahi + (size_t)ra * lda + lhalf * 8;
    const __nv_bfloat16* pAl = Alo + (size_t)ra * lda + lhalf * 8;
    const __nv_bfloat16* pBh = Bhi + (size_t)rb * ldb + lhalf * 8;
    const __nv_bfloat16* pBl = Blo + (size_t)rb * ldb + lhalf * 8;
    const uint32_t doff = (uint32_t)(lrow * TSTRIDE + lhalf * 16);

    const int NIT = K >> 4;

    auto issue_stage = [&](int it, int buf) {
        const int kt = it << 4;
        const uint32_t sb = sbase + buf * STAGE_SZ + doff;
        asm volatile("cp.async.cg.shared.global [%0], [%1], 16, %2;"
                     :: "r"(sb), "l"(pAh + kt), "r"(asz));
        asm volatile("cp.async.cg.shared.global [%0], [%1], 16, %2;"
                     :: "r"(sb + TILE_SZ), "l"(pAl + kt), "r"(asz));
        asm volatile("cp.async.cg.shared.global [%0], [%1], 16;"
                     :: "r"(sb + 2 * TILE_SZ), "l"(pBh + kt));
        asm volatile("cp.async.cg.shared.global [%0], [%1], 16;"
                     :: "r"(sb + 3 * TILE_SZ), "l"(pBl + kt));
        asm volatile("cp.async.commit_group;" ::: "memory");
    };

    issue_stage(0, 0);
    if (NIT > 1) issue_stage(1, 1);

    int buf = 0, nbuf = 2;
    for (int it = 0; it < NIT; it++) {
        if (it + 1 < NIT) {
            asm volatile("cp.async.wait_group 1;" ::: "memory");
        } else {
            asm volatile("cp.async.wait_group 0;" ::: "memory");
        }
        __syncthreads();

        if (it + 2 < NIT) issue_stage(it + 2, nbuf);

        const uint32_t stg = sbase + buf * STAGE_SZ;
        #pragma unroll
        for (int pass = 0; pass < 3; pass++) {
            const uint32_t abase = stg + (pass == 2 ? TILE_SZ : 0) + warp_m * TSTRIDE;
            const uint32_t bbase = stg + (pass == 1 ? 3 * TILE_SZ : 2 * TILE_SZ) + warp_n * TSTRIDE;
            uint32_t afrag[2][4];
            #pragma unroll
            for (int mi = 0; mi < 2; mi++)
                ldsm4(abase + mi * 16 * TSTRIDE + aoff,
                      afrag[mi][0], afrag[mi][1], afrag[mi][2], afrag[mi][3]);
            #pragma unroll
            for (int nj2 = 0; nj2 < 4; nj2++) {
                uint32_t b0, b1, b2, b3;
                ldsm4(bbase + nj2 * 16 * TSTRIDE + boff, b0, b1, b2, b3);
                mma16816(acc[0][nj2 * 2 + 0], afrag[0], b0, b1);
                mma16816(acc[0][nj2 * 2 + 1], afrag[0], b2, b3);
                mma16816(acc[1][nj2 * 2 + 0], afrag[1], b0, b1);
                mma16816(acc[1][nj2 * 2 + 1], afrag[1], b2, b3);
            }
        }
        buf = (buf == NSTAGE - 1) ? 0 : buf + 1;
        nbuf = (nbuf == NSTAGE - 1) ? 0 : nbuf + 1;
    }

    const int qrow = lane >> 2, qcol = (lane & 3) * 2;
    #pragma unroll
    for (int mi = 0; mi < 2; mi++) {
        #pragma unroll
        for (int half = 0; half < 2; half++) {
            int r = bm + warp_m + mi * 16 + half * 8 + qrow;
            if (r < M) {
                #pragma unroll
                for (int nj = 0; nj < 8; nj++) {
                    int c = bn + warp_n + nj * 8 + qcol;
                    float2 v;
                    v.x = acc[mi][nj][half * 2 + 0];
                    v.y = acc[mi][nj][half * 2 + 1];
                    if (has_bias) {
                        v.x += bias[c];
                        v.y += bias[c + 1];
                    }
                    *(float2*)(C + (size_t)r * ldc + c) = v;
                }
            }
        }
    }
}

// ---------------- fused gather: xc_slab[n] = gelu(t[n]*dinv^2 + b + sum_nbr t[s]*dinv_s*dinv_n)
__global__ __launch_bounds__(128)
void gather_kernel(const float* __restrict__ b, int layer)
{
    const int n = blockIdx.x;
    const int c = threadIdx.x << 2;
    const float din = g_dinv[n];
    const float sl = din * din;

    float4 tv = *(const float4*)(g_t + (size_t)n * DIM + c);
    const float4 bb = *(const float4*)(b + c);
    float4 acc;
    acc.x = tv.x * sl + bb.x;
    acc.y = tv.y * sl + bb.y;
    acc.z = tv.z * sl + bb.z;
    acc.w = tv.w * sl + bb.w;

    const int beg = g_rowptr[n], end = g_rowptr[n + 1];
    int j = beg;
    for (; j + 4 <= end; j += 4) {
        int s0 = __ldg(&g_esrc[j + 0]);
        int s1 = __ldg(&g_esrc[j + 1]);
        int s2 = __ldg(&g_esrc[j + 2]);
        int s3 = __ldg(&g_esrc[j + 3]);
        float w0 = __ldg(&g_dinv[s0]) * din;
        float w1 = __ldg(&g_dinv[s1]) * din;
        float w2 = __ldg(&g_dinv[s2]) * din;
        float w3 = __ldg(&g_dinv[s3]) * din;
        float4 v0 = *(const float4*)(g_t + (size_t)s0 * DIM + c);
        float4 v1 = *(const float4*)(g_t + (size_t)s1 * DIM + c);
        float4 v2 = *(const float4*)(g_t + (size_t)s2 * DIM + c);
        float4 v3 = *(const float4*)(g_t + (size_t)s3 * DIM + c);
        acc.x += v0.x * w0 + v1.x * w1 + v2.x * w2 + v3.x * w3;
        acc.y += v0.y * w0 + v1.y * w1 + v2.y * w2 + v3.y * w3;
        acc.z += v0.z * w0 + v1.z * w1 + v2.z * w2 + v3.z * w3;
        acc.w += v0.w * w0 + v1.w * w1 + v2.w * w2 + v3.w * w3;
    }
    for (; j < end; j++) {
        int s = __ldg(&g_esrc[j]);
        float w = __ldg(&g_dinv[s]) * din;
        float4 v = *(const float4*)(g_t + (size_t)s * DIM + c);
        acc.x += v.x * w;
        acc.y += v.y * w;
        acc.z += v.z * w;
        acc.w += v.w * w;
    }

    float4 r;
    r.x = gelu_exact(acc.x);
    r.y = gelu_exact(acc.y);
    r.z = gelu_exact(acc.z);
    r.w = gelu_exact(acc.w);
    size_t o = (size_t)n * INNER + (size_t)layer * DIM + c;
    uint2 uh, ul; split4(r, uh, ul);
    *(uint2*)(g_xch + o) = uh;
    *(uint2*)(g_xcl + o) = ul;
}

// ---------------- BatchNorm statistics: vectorized (8 bf16 per plane per load) ----------------
// 256 threads: thread t owns cols [8t, 8t+8); grid.x = row chunks.
__global__ __launch_bounds__(256)
void bn_stats_kernel(int rows_per_chunk) {
    const int c0 = threadIdx.x * 8;
    const int r0 = blockIdx.x * rows_per_chunk;
    float s[8], s2[8];
    #pragma unroll
    for (int i = 0; i < 8; i++) { s[i] = 0.f; s2[i] = 0.f; }

    for (int r = r0; r < r0 + rows_per_chunk; r++) {
        size_t o = (size_t)r * INNER + c0;
        union { uint4 u; __nv_bfloat16 b[8]; } H, L;
        H.u = *(const uint4*)(g_xch + o);
        L.u = *(const uint4*)(g_xcl + o);
        #pragma unroll
        for (int i = 0; i < 8; i++) {
            float v = __bfloat162float(H.b[i]) + __bfloat162float(L.b[i]);
            s[i]  += v;
            s2[i] += v * v;
        }
    }
    #pragma unroll
    for (int i = 0; i < 8; i++) {
        atomicAdd(&g_sum[c0 + i],   s[i]);
        atomicAdd(&g_sumsq[c0 + i], s2[i]);
    }
}

__global__ void scale_shift_kernel(const float* __restrict__ gamma,
                                   const float* __restrict__ beta)
{
    int c = blockIdx.x * blockDim.x + threadIdx.x;
    if (c < INNER) {
        const float invN = 1.0f / (float)N_NODES;
        float mean = g_sum[c] * invN;
        float var  = g_sumsq[c] * invN - mean * mean;
        float sc = gamma[c] * rsqrtf(var + EPSBN);
        g_scale[c] = sc;
        g_shift[c] = beta[c] - mean * sc;
    }
}

__global__ void biasp_init_kernel(const float* __restrict__ outb) {
    int d = blockIdx.x * blockDim.x + threadIdx.x;
    if (d < DIM) g_biasp[d] = outb[d];
}

__global__ void biasp_acc_kernel(const float* __restrict__ outW) {
    int d = threadIdx.x;
    int c0 = blockIdx.x * 128;
    float s = 0.f;
    for (int c = c0; c < c0 + 128; c++)
        s += g_shift[c] * outW[(size_t)c * DIM + d];
    atomicAdd(&g_biasp[d], s);
}

// ---------------- launch ----------------
extern "C" void kernel_launch(void* const* d_in, const int* in_sizes, int n_in,
                              void* d_out, int out_size)
{
    const float* x     = (const float*)d_in[0];
    const int*   ei    = (const int*)d_in[1];
    const float* Ws    = (const float*)d_in[2];
    const float* bs    = (const float*)d_in[3];
    const float* gamma = (const float*)d_in[4];
    const float* beta  = (const float*)d_in[5];
    const float* outW  = (const float*)d_in[6];
    const float* outb  = (const float*)d_in[7];
    float*       out   = (float*)d_out;

    float *t, *biasp;
    __nv_bfloat16 *xch, *xcl, *Wth, *Wtl, *Wpth, *Wptl;
    cudaGetSymbolAddress((void**)&t,     g_t);
    cudaGetSymbolAddress((void**)&biasp, g_biasp);
    cudaGetSymbolAddress((void**)&xch,   g_xch);
    cudaGetSymbolAddress((void**)&xcl,   g_xcl);
    cudaGetSymbolAddress((void**)&Wth,   g_Wth);
    cudaGetSymbolAddress((void**)&Wtl,   g_Wtl);
    cudaGetSymbolAddress((void**)&Wpth,  g_Wpth);
    cudaGetSymbolAddress((void**)&Wptl,  g_Wptl);

    cudaFuncSetAttribute(mma_gemm_kernel,
                         cudaFuncAttributeMaxDynamicSharedMemorySize, GEMM_SMEM);

    const int NF4 = N_NODES * (DIM / 4);
    dim3 gemm_grid(4, (N_NODES + 127) / 128);    // (4, 391)

    // CSR build + dinv
    zero_int_kernel<<<(N_NODES + 255) / 256, 256>>>();
    count_kernel<<<(N_EDGES + 255) / 256, 256>>>(ei);
    scan_kernel<<<1, 1024>>>();
    fill_kernel<<<(N_EDGES + 255) / 256, 256>>>(ei);
    dinv_kernel<<<(N_NODES + 255) / 256, 256>>>();

    // x -> concat slab 0 (bf16 planes); weight transpose+split
    copy_x_kernel<<<NF4 / 256, 256>>>(x);
    wt_kernel<<<(LAYERS * DIM * DIM + 255) / 256, 256>>>(Ws);

    // GCN layers
    for (int l = 0; l < LAYERS; l++) {
        mma_gemm_kernel<<<gemm_grid, 256, GEMM_SMEM>>>(
            xch + (size_t)l * DIM, xcl + (size_t)l * DIM,
            Wth + (size_t)l * DIM * DIM, Wtl + (size_t)l * DIM * DIM,
            nullptr, t, N_NODES, DIM, INNER, DIM, DIM, 0);
        gather_kernel<<<N_NODES, 128>>>(bs + (size_t)l * DIM, l + 1);
    }

    // BatchNorm statistics + fold into head GEMM
    zero_stats_kernel<<<INNER / 256, 256>>>();
    bn_stats_kernel<<<250, 256>>>(N_NODES / 250);
    scale_shift_kernel<<<INNER / 256, 256>>>(gamma, beta);
    wpt_kernel<<<(INNER * DIM + 255) / 256, 256>>>(outW);
    biasp_init_kernel<<<(DIM + 255) / 256, 256>>>(outb);
    biasp_acc_kernel<<<INNER / 128, DIM>>>(outW);

    // head GEMM: out = xc @ Wp + biasp
    mma_gemm_kernel<<<gemm_grid, 256, GEMM_SMEM>>>(
        xch, xcl, Wpth, Wptl, biasp, out, N_NODES, INNER, INNER, INNER, DIM, 1);
}

// round 16
// speedup vs baseline: 1.2318x; 1.2318x over previous
#include <cuda_runtime.h>
#include <cuda_bf16.h>
#include <math.h>
#include <stdint.h>

#define N_NODES 50000
#define N_EDGES 400000
#define DIM     512
#define LAYERS  3
#define INNER   2048      // (LAYERS+1)*DIM
#define EPSBN   1e-5f

// ---------------- static device scratch (no allocations allowed) ----------------
__device__ __nv_bfloat16 g_xch[(size_t)N_NODES * INNER];  // bf16 hi plane of xc
__device__ __nv_bfloat16 g_xcl[(size_t)N_NODES * INNER];  // bf16 lo plane of xc
__device__ float g_t  [(size_t)N_NODES * DIM];     // h @ W (layer GEMM out, fp32)
__device__ float g_dinv[N_NODES];
__device__ int   g_cnt [N_NODES];                  // in-degree
__device__ int   g_rowptr[N_NODES + 1];
__device__ int   g_fill[N_NODES];
__device__ int   g_esrc[N_EDGES];                  // CSR: src node per (dst-sorted) edge
__device__ float g_sum  [INNER];
__device__ float g_sumsq[INNER];
__device__ float g_scale[INNER];
__device__ float g_shift[INNER];
__device__ float g_biasp[DIM];                     // shift-folded head bias
// transposed + split weights: Bt[n, k] (K-major rows)
__device__ __nv_bfloat16 g_Wth[(size_t)LAYERS * DIM * DIM];
__device__ __nv_bfloat16 g_Wtl[(size_t)LAYERS * DIM * DIM];
__device__ __nv_bfloat16 g_Wpth[(size_t)DIM * INNER];   // head: [512, 2048]
__device__ __nv_bfloat16 g_Wptl[(size_t)DIM * INNER];

// ---------------- helpers ----------------
__device__ __forceinline__ float gelu_exact(float v) {
    return 0.5f * v * (1.0f + erff(v * 0.70710678118654752440f));
}

__device__ __forceinline__ uint32_t smem_u32(const void* p) {
    uint32_t a;
    asm("{ .reg .u64 t; cvta.to.shared.u64 t, %1; cvt.u32.u64 %0, t; }" : "=r"(a) : "l"(p));
    return a;
}

// split fp32 -> bf16 hi + bf16 lo (packed 4-wide)
__device__ __forceinline__ void split4(float4 v, uint2& uh, uint2& ul) {
    union { __nv_bfloat16 b[4]; uint2 u; } H, L;
    H.b[0] = __float2bfloat16(v.x); L.b[0] = __float2bfloat16(v.x - __bfloat162float(H.b[0]));
    H.b[1] = __float2bfloat16(v.y); L.b[1] = __float2bfloat16(v.y - __bfloat162float(H.b[1]));
    H.b[2] = __float2bfloat16(v.z); L.b[2] = __float2bfloat16(v.z - __bfloat162float(H.b[2]));
    H.b[3] = __float2bfloat16(v.w); L.b[3] = __float2bfloat16(v.w - __bfloat162float(H.b[3]));
    uh = H.u; ul = L.u;
}

__device__ __forceinline__ void ldsm4(uint32_t addr, uint32_t& r0, uint32_t& r1,
                                      uint32_t& r2, uint32_t& r3) {
    asm volatile("ldmatrix.sync.aligned.m8n8.x4.shared.b16 {%0,%1,%2,%3}, [%4];"
                 : "=r"(r0), "=r"(r1), "=r"(r2), "=r"(r3) : "r"(addr));
}

__device__ __forceinline__ void mma16816(float* c, const uint32_t* a,
                                         uint32_t b0, uint32_t b1) {
    asm volatile(
        "mma.sync.aligned.m16n8k16.row.col.f32.bf16.bf16.f32 "
        "{%0,%1,%2,%3}, {%4,%5,%6,%7}, {%8,%9}, {%0,%1,%2,%3};"
        : "+f"(c[0]), "+f"(c[1]), "+f"(c[2]), "+f"(c[3])
        : "r"(a[0]), "r"(a[1]), "r"(a[2]), "r"(a[3]), "r"(b0), "r"(b1));
}

// ---------------- CSR build ----------------
__global__ void zero_int_kernel() {
    int n = blockIdx.x * blockDim.x + threadIdx.x;
    if (n < N_NODES) { g_cnt[n] = 0; g_fill[n] = 0; }
}
__global__ void count_kernel(const int* __restrict__ ei) {
    int e = blockIdx.x * blockDim.x + threadIdx.x;
    if (e < N_EDGES) atomicAdd(&g_cnt[ei[N_EDGES + e]], 1);
}
__global__ void scan_kernel() {
    __shared__ int partial[1024];
    const int t = threadIdx.x;
    const int chunk = (N_NODES + 1023) / 1024;
    const int start = t * chunk;
    const int end = min(start + chunk, N_NODES);
    int s = 0;
    for (int i = start; i < end; i++) s += g_cnt[i];
    partial[t] = s;
    __syncthreads();
    #pragma unroll
    for (int off = 1; off < 1024; off <<= 1) {
        int v = (t >= off) ? partial[t - off] : 0;
        __syncthreads();
        partial[t] += v;
        __syncthreads();
    }
    int run = partial[t] - s;
    for (int i = start; i < end; i++) { g_rowptr[i] = run; run += g_cnt[i]; }
    if (t == 1023) g_rowptr[N_NODES] = run;
}
__global__ void fill_kernel(const int* __restrict__ ei) {
    int e = blockIdx.x * blockDim.x + threadIdx.x;
    if (e < N_EDGES) {
        int s = ei[e];
        int d = ei[N_EDGES + e];
        int pos = g_rowptr[d] + atomicAdd(&g_fill[d], 1);
        g_esrc[pos] = s;
    }
}
__global__ void dinv_kernel() {
    int n = blockIdx.x * blockDim.x + threadIdx.x;
    if (n < N_NODES) g_dinv[n] = rsqrtf((float)g_cnt[n] + 1.0f);
}

__global__ void zero_stats_kernel() {
    int c = blockIdx.x * blockDim.x + threadIdx.x;
    if (c < INNER) { g_sum[c] = 0.0f; g_sumsq[c] = 0.0f; }
}

// ---------------- copy x into concat slab 0 (bf16 hi/lo planes) ----------------
__global__ void copy_x_kernel(const float* __restrict__ x) {
    int i = blockIdx.x * blockDim.x + threadIdx.x;    // N_NODES*128 float4 units
    int n = i >> 7;
    int c = (i & 127) << 2;
    float4 v = *(const float4*)(x + (size_t)n * DIM + c);
    size_t o = (size_t)n * INNER + c;
    uint2 uh, ul; split4(v, uh, ul);
    *(uint2*)(g_xch + o) = uh;
    *(uint2*)(g_xcl + o) = ul;
}

// ---------------- transpose+split layer weights: Wt[l][n][k] = W[l][k][n] ----------------
__global__ void wt_kernel(const float* __restrict__ Ws) {
    int i = blockIdx.x * blockDim.x + threadIdx.x;    // 3*512*512
    if (i >= LAYERS * DIM * DIM) return;
    int l = i >> 18, rem = i & 262143, k = rem >> 9, n = rem & 511;
    float w = Ws[(size_t)l * DIM * DIM + (size_t)k * DIM + n];
    __nv_bfloat16 h = __float2bfloat16(w);
    size_t o = (size_t)l * DIM * DIM + (size_t)n * DIM + k;
    g_Wth[o] = h;
    g_Wtl[o] = __float2bfloat16(w - __bfloat162float(h));
}

// ---------------- scaled head weight transpose+split ----------------
__global__ void wpt_kernel(const float* __restrict__ outW) {
    int i = blockIdx.x * blockDim.x + threadIdx.x;    // 2048*512
    if (i >= INNER * DIM) return;
    int k = i >> 9, n = i & 511;
    float w = outW[i] * g_scale[k];
    __nv_bfloat16 h = __float2bfloat16(w);
    size_t o = (size_t)n * INNER + k;
    g_Wpth[o] = h;
    g_Wptl[o] = __float2bfloat16(w - __bfloat162float(h));
}

// ---------------- cp.async double-buffered split-bf16 GEMM: C = A @ B^T (+bias) ----------------
// ROUND-11 STRUCTURE (empirical best). Tile 128x128, K_tile=16, 2 stages.
// SMEM: 2 x 4 tiles x 128 rows x 48B stride = 48KB static.
#define TSTRIDE 48
#define TILE_SZ (128 * TSTRIDE)      // 6144
#define STAGE_SZ (4 * TILE_SZ)       // 24576

__global__ __launch_bounds__(256)
void mma_gemm_kernel(const __nv_bfloat16* __restrict__ Ahi, const __nv_bfloat16* __restrict__ Alo,
                     const __nv_bfloat16* __restrict__ Bhi, const __nv_bfloat16* __restrict__ Blo,
                     const float* __restrict__ bias, float* __restrict__ C,
                     int M, int K, int lda, int ldb, int ldc, int has_bias)
{
    __shared__ char smem[2 * STAGE_SZ];   // 48KB (static limit, no opt-in needed)

    const int tid = threadIdx.x, wid = tid >> 5, lane = tid & 31;
    const int bm = blockIdx.y * 128, bn = blockIdx.x * 128;
    const int warp_m = (wid & 3) * 32, warp_n = (wid >> 2) * 64;
    const uint32_t sbase = smem_u32(smem);

    float acc[2][8][4];
    #pragma unroll
    for (int a = 0; a < 2; a++)
        #pragma unroll
        for (int b = 0; b < 8; b++)
            #pragma unroll
            for (int c = 0; c < 4; c++) acc[a][b][c] = 0.0f;

    const uint32_t aoff = (uint32_t)(((lane & 7) + ((lane >> 3) & 1) * 8) * TSTRIDE + (lane >> 4) * 16);
    const uint32_t boff = (uint32_t)(((lane & 7) + (lane >> 4) * 8) * TSTRIDE + ((lane >> 3) & 1) * 16);

    const int NIT = K >> 4;

    // ---- async load of one K_tile=16 stage: 4 tiles x 128 rows x 32B = 1024 x 16B
    auto issue_stage = [&](int it, int buf) {
        const int kt = it << 4;
        const uint32_t sb = sbase + buf * STAGE_SZ;
        #pragma unroll
        for (int i = tid; i < 1024; i += 256) {
            int tile = i >> 8, idx = i & 255, row = idx >> 1, half = idx & 1;
            const __nv_bfloat16* src;
            int sz = 16;
            if (tile < 2) {
                int r = bm + row;
                if (r >= M) { r = 0; sz = 0; }
                src = (tile ? Alo : Ahi) + (size_t)r * lda + kt + half * 8;
            } else {
                int r = bn + row;
                src = (tile == 3 ? Blo : Bhi) + (size_t)r * ldb + kt + half * 8;
            }
            uint32_t dst = sb + tile * TILE_SZ + (uint32_t)(row * TSTRIDE + half * 16);
            asm volatile("cp.async.cg.shared.global [%0], [%1], 16, %2;"
                         :: "r"(dst), "l"(src), "r"(sz));
        }
        asm volatile("cp.async.commit_group;" ::: "memory");
    };

    issue_stage(0, 0);

    for (int it = 0; it < NIT; it++) {
        if (it + 1 < NIT) {
            issue_stage(it + 1, (it + 1) & 1);
            asm volatile("cp.async.wait_group 1;" ::: "memory");
        } else {
            asm volatile("cp.async.wait_group 0;" ::: "memory");
        }
        __syncthreads();

        const uint32_t stg = sbase + (it & 1) * STAGE_SZ;
        #pragma unroll
        for (int pass = 0; pass < 3; pass++) {
            const uint32_t abase = stg + (pass == 2 ? TILE_SZ : 0) + warp_m * TSTRIDE;
            const uint32_t bbase = stg + (pass == 1 ? 3 * TILE_SZ : 2 * TILE_SZ) + warp_n * TSTRIDE;
            uint32_t afrag[2][4];
            #pragma unroll
            for (int mi = 0; mi < 2; mi++)
                ldsm4(abase + mi * 16 * TSTRIDE + aoff,
                      afrag[mi][0], afrag[mi][1], afrag[mi][2], afrag[mi][3]);
            #pragma unroll
            for (int nj2 = 0; nj2 < 4; nj2++) {
                uint32_t b0, b1, b2, b3;
                ldsm4(bbase + nj2 * 16 * TSTRIDE + boff, b0, b1, b2, b3);
                mma16816(acc[0][nj2 * 2 + 0], afrag[0], b0, b1);
                mma16816(acc[0][nj2 * 2 + 1], afrag[0], b2, b3);
                mma16816(acc[1][nj2 * 2 + 0], afrag[1], b0, b1);
                mma16816(acc[1][nj2 * 2 + 1], afrag[1], b2, b3);
            }
        }
        __syncthreads();
    }

    const int qrow = lane >> 2, qcol = (lane & 3) * 2;
    #pragma unroll
    for (int mi = 0; mi < 2; mi++) {
        #pragma unroll
        for (int half = 0; half < 2; half++) {
            int r = bm + warp_m + mi * 16 + half * 8 + qrow;
            if (r < M) {
                #pragma unroll
                for (int nj = 0; nj < 8; nj++) {
                    int c = bn + warp_n + nj * 8 + qcol;
                    float2 v;
                    v.x = acc[mi][nj][half * 2 + 0];
                    v.y = acc[mi][nj][half * 2 + 1];
                    if (has_bias) {
                        v.x += bias[c];
                        v.y += bias[c + 1];
                    }
                    *(float2*)(C + (size_t)r * ldc + c) = v;
                }
            }
        }
    }
}

// ---------------- fused gather: xc_slab[n] = gelu(t[n]*dinv^2 + b + sum_nbr t[s]*dinv_s*dinv_n)
__global__ __launch_bounds__(128)
void gather_kernel(const float* __restrict__ b, int layer)
{
    const int n = blockIdx.x;
    const int c = threadIdx.x << 2;
    const float din = g_dinv[n];
    const float sl = din * din;

    float4 tv = *(const float4*)(g_t + (size_t)n * DIM + c);
    const float4 bb = *(const float4*)(b + c);
    float4 acc;
    acc.x = tv.x * sl + bb.x;
    acc.y = tv.y * sl + bb.y;
    acc.z = tv.z * sl + bb.z;
    acc.w = tv.w * sl + bb.w;

    const int beg = g_rowptr[n], end = g_rowptr[n + 1];
    int j = beg;
    for (; j + 4 <= end; j += 4) {
        int s0 = __ldg(&g_esrc[j + 0]);
        int s1 = __ldg(&g_esrc[j + 1]);
        int s2 = __ldg(&g_esrc[j + 2]);
        int s3 = __ldg(&g_esrc[j + 3]);
        float w0 = __ldg(&g_dinv[s0]) * din;
        float w1 = __ldg(&g_dinv[s1]) * din;
        float w2 = __ldg(&g_dinv[s2]) * din;
        float w3 = __ldg(&g_dinv[s3]) * din;
        float4 v0 = *(const float4*)(g_t + (size_t)s0 * DIM + c);
        float4 v1 = *(const float4*)(g_t + (size_t)s1 * DIM + c);
        float4 v2 = *(const float4*)(g_t + (size_t)s2 * DIM + c);
        float4 v3 = *(const float4*)(g_t + (size_t)s3 * DIM + c);
        acc.x += v0.x * w0 + v1.x * w1 + v2.x * w2 + v3.x * w3;
        acc.y += v0.y * w0 + v1.y * w1 + v2.y * w2 + v3.y * w3;
        acc.z += v0.z * w0 + v1.z * w1 + v2.z * w2 + v3.z * w3;
        acc.w += v0.w * w0 + v1.w * w1 + v2.w * w2 + v3.w * w3;
    }
    for (; j < end; j++) {
        int s = __ldg(&g_esrc[j]);
        float w = __ldg(&g_dinv[s]) * din;
        float4 v = *(const float4*)(g_t + (size_t)s * DIM + c);
        acc.x += v.x * w;
        acc.y += v.y * w;
        acc.z += v.z * w;
        acc.w += v.w * w;
    }

    float4 r;
    r.x = gelu_exact(acc.x);
    r.y = gelu_exact(acc.y);
    r.z = gelu_exact(acc.z);
    r.w = gelu_exact(acc.w);
    size_t o = (size_t)n * INNER + (size_t)layer * DIM + c;
    uint2 uh, ul; split4(r, uh, ul);
    *(uint2*)(g_xch + o) = uh;
    *(uint2*)(g_xcl + o) = ul;
}

// ---------------- BatchNorm statistics: vectorized (8 bf16 per plane per load) ----------------
// 256 threads: thread t owns cols [8t, 8t+8); grid.x = row chunks.
__global__ __launch_bounds__(256)
void bn_stats_kernel(int rows_per_chunk) {
    const int c0 = threadIdx.x * 8;
    const int r0 = blockIdx.x * rows_per_chunk;
    float s[8], s2[8];
    #pragma unroll
    for (int i = 0; i < 8; i++) { s[i] = 0.f; s2[i] = 0.f; }

    for (int r = r0; r < r0 + rows_per_chunk; r++) {
        size_t o = (size_t)r * INNER + c0;
        union { uint4 u; __nv_bfloat16 b[8]; } H, L;
        H.u = *(const uint4*)(g_xch + o);
        L.u = *(const uint4*)(g_xcl + o);
        #pragma unroll
        for (int i = 0; i < 8; i++) {
            float v = __bfloat162float(H.b[i]) + __bfloat162float(L.b[i]);
            s[i]  += v;
            s2[i] += v * v;
        }
    }
    #pragma unroll
    for (int i = 0; i < 8; i++) {
        atomicAdd(&g_sum[c0 + i],   s[i]);
        atomicAdd(&g_sumsq[c0 + i], s2[i]);
    }
}

__global__ void scale_shift_kernel(const float* __restrict__ gamma,
                                   const float* __restrict__ beta)
{
    int c = blockIdx.x * blockDim.x + threadIdx.x;
    if (c < INNER) {
        const float invN = 1.0f / (float)N_NODES;
        float mean = g_sum[c] * invN;
        float var  = g_sumsq[c] * invN - mean * mean;
        float sc = gamma[c] * rsqrtf(var + EPSBN);
        g_scale[c] = sc;
        g_shift[c] = beta[c] - mean * sc;
    }
}

__global__ void biasp_init_kernel(const float* __restrict__ outb) {
    int d = blockIdx.x * blockDim.x + threadIdx.x;
    if (d < DIM) g_biasp[d] = outb[d];
}

__global__ void biasp_acc_kernel(const float* __restrict__ outW) {
    int d = threadIdx.x;
    int c0 = blockIdx.x * 128;
    float s = 0.f;
    for (int c = c0; c < c0 + 128; c++)
        s += g_shift[c] * outW[(size_t)c * DIM + d];
    atomicAdd(&g_biasp[d], s);
}

// ---------------- launch ----------------
extern "C" void kernel_launch(void* const* d_in, const int* in_sizes, int n_in,
                              void* d_out, int out_size)
{
    const float* x     = (const float*)d_in[0];
    const int*   ei    = (const int*)d_in[1];
    const float* Ws    = (const float*)d_in[2];
    const float* bs    = (const float*)d_in[3];
    const float* gamma = (const float*)d_in[4];
    const float* beta  = (const float*)d_in[5];
    const float* outW  = (const float*)d_in[6];
    const float* outb  = (const float*)d_in[7];
    float*       out   = (float*)d_out;

    float *t, *biasp;
    __nv_bfloat16 *xch, *xcl, *Wth, *Wtl, *Wpth, *Wptl;
    cudaGetSymbolAddress((void**)&t,     g_t);
    cudaGetSymbolAddress((void**)&biasp, g_biasp);
    cudaGetSymbolAddress((void**)&xch,   g_xch);
    cudaGetSymbolAddress((void**)&xcl,   g_xcl);
    cudaGetSymbolAddress((void**)&Wth,   g_Wth);
    cudaGetSymbolAddress((void**)&Wtl,   g_Wtl);
    cudaGetSymbolAddress((void**)&Wpth,  g_Wpth);
    cudaGetSymbolAddress((void**)&Wptl,  g_Wptl);

    const int NF4 = N_NODES * (DIM / 4);
    dim3 gemm_grid(4, (N_NODES + 127) / 128);    // (4, 391)

    // CSR build + dinv
    zero_int_kernel<<<(N_NODES + 255) / 256, 256>>>();
    count_kernel<<<(N_EDGES + 255) / 256, 256>>>(ei);
    scan_kernel<<<1, 1024>>>();
    fill_kernel<<<(N_EDGES + 255) / 256, 256>>>(ei);
    dinv_kernel<<<(N_NODES + 255) / 256, 256>>>();

    // x -> concat slab 0 (bf16 planes); weight transpose+split
    copy_x_kernel<<<NF4 / 256, 256>>>(x);
    wt_kernel<<<(LAYERS * DIM * DIM + 255) / 256, 256>>>(Ws);

    // GCN layers
    for (int l = 0; l < LAYERS; l++) {
        mma_gemm_kernel<<<gemm_grid, 256>>>(
            xch + (size_t)l * DIM, xcl + (size_t)l * DIM,
            Wth + (size_t)l * DIM * DIM, Wtl + (size_t)l * DIM * DIM,
            nullptr, t, N_NODES, DIM, INNER, DIM, DIM, 0);
        gather_kernel<<<N_NODES, 128>>>(bs + (size_t)l * DIM, l + 1);
    }

    // BatchNorm statistics + fold into head GEMM
    zero_stats_kernel<<<INNER / 256, 256>>>();
    bn_stats_kernel<<<250, 256>>>(N_NODES / 250);
    scale_shift_kernel<<<INNER / 256, 256>>>(gamma, beta);
    wpt_kernel<<<(INNER * DIM + 255) / 256, 256>>>(outW);
    biasp_init_kernel<<<(DIM + 255) / 256, 256>>>(outb);
    biasp_acc_kernel<<<INNER / 128, DIM>>>(outW);

    // head GEMM: out = xc @ Wp + biasp
    mma_gemm_kernel<<<gemm_grid, 256>>>(
        xch, xcl, Wpth, Wptl, biasp, out, N_NODES, INNER, INNER, INNER, DIM, 1);
}